// round 10
// baseline (speedup 1.0000x reference)
#include <cuda_runtime.h>

#define THR 0.5f
#define MIN_JUMP_ENERGY 0.5f
#define MIN_VELOCITY_THRESHOLD 0.1f
#define MIN_WALL_JUMP_SPEED 1.0f

static constexpr int B = 32;
static constexpr int E = 100000;
static constexpr int NROWS = B * E;          // 3,200,000 — divisible by 256
static constexpr int NBLK  = NROWS / 256;    // 12,500 full CTAs, no tail

__global__ __launch_bounds__(256) void edge_mask_kernel(
    const float4* __restrict__ feat,     // [B, E, 16] viewed as float4[B*E*4]
    const float*  __restrict__ phys,     // [B, 18]
    const float*  __restrict__ base,     // [B, E]
    float*        __restrict__ out)      // [B, E]
{
    const int row32 = blockIdx.x * 256 + threadIdx.x;   // flat row in [0, B*E)
    const int b = row32 / E;                            // const-div -> mulhi+shift; warp-uniform (E%32==0)

    const size_t row = (size_t)row32;
    const float4* f = feat + row * 4;

    // Front-batched streaming loads (MLP_p1 = 5)
    const float4 f0 = __ldcs(f + 0);   // cols 0-3
    const float4 f1 = __ldcs(f + 1);   // cols 4-7
    const float4 f2 = __ldcs(f + 2);   // cols 8-11
    const float4 f3 = __ldcs(f + 3);   // cols 12-15
    const float  bval = __ldcs(base + row);

    // Per-batch physics scalars (warp-uniform; cached)
    const float* p = phys + b * 18;
    const float vel  = p[2];
    const float wall = p[5];
    const float ke   = p[9];
    const float cj   = p[16];
    const float cwj  = p[17];

    // argmax over cols 0..5, first-max-wins (strict >)
    int   et = 0;
    float mx = f0.x;
    if (f0.y > mx) { mx = f0.y; et = 1; }
    if (f0.z > mx) { mx = f0.z; et = 2; }
    if (f0.w > mx) { mx = f0.w; et = 3; }
    if (f1.x > mx) { mx = f1.x; et = 4; }
    if (f1.y > mx) { mx = f1.y; et = 5; }

    const float energy_cost           = f2.z;  // col 10
    const float min_velocity          = f3.x;  // col 12
    const float max_velocity          = f3.y;  // col 13
    const float requires_jump         = f3.z;  // col 14
    const float requires_wall_contact = f3.w;  // col 15

    // jnp.select: first-true-wins priority chain
    const bool cc1 = (et == 1) && (cj < THR);
    const bool cc2 = (et == 3);
    const bool d2  = (wall < THR) || (vel < MIN_VELOCITY_THRESHOLD);
    const bool cc3 = (requires_jump > THR);
    const bool d3  = (cj < THR) || (vel < min_velocity);
    const bool cc4 = (requires_wall_contact > THR);
    const bool d4  = (wall < THR) ||
                     ((cwj < THR) && (vel < MIN_WALL_JUMP_SPEED));
    const bool cc5 = (et == 1);
    const bool d5  = (ke < energy_cost * MIN_JUMP_ENERGY);

    bool dis;
    if      (cc1) dis = true;
    else if (cc2) dis = d2;
    else if (cc3) dis = d3;
    else if (cc4) dis = d4;
    else if (cc5) dis = d5;
    else          dis = false;

    const bool over  = (max_velocity > 0.0f) && (vel > max_velocity);
    const bool under = (!over) && (vel < min_velocity);
    dis = dis || over || under;

    __stcs(out + row, dis ? 0.0f : bval);
}

extern "C" void kernel_launch(void* const* d_in, const int* in_sizes, int n_in,
                              void* d_out, int out_size)
{
    const float4* feat = (const float4*)d_in[0];
    const float*  phys = (const float*) d_in[1];
    const float*  base = (const float*) d_in[2];
    float*        out  = (float*)d_out;

    edge_mask_kernel<<<NBLK, 256>>>(feat, phys, base, out);
}

// round 11
// speedup vs baseline: 1.0643x; 1.0643x over previous
#include <cuda_runtime.h>

#define THR 0.5f
#define MIN_JUMP_ENERGY 0.5f
#define MIN_VELOCITY_THRESHOLD 0.1f
#define MIN_WALL_JUMP_SPEED 1.0f

static constexpr int B = 32;
static constexpr int E = 100000;

__global__ __launch_bounds__(256) void edge_mask_kernel(
    const float4* __restrict__ feat,     // [B, E, 16] viewed as float4[B*E*4]
    const float*  __restrict__ phys,     // [B, 18]
    const float*  __restrict__ base,     // [B, E]
    float*        __restrict__ out)      // [B, E]
{
    const int b = blockIdx.y;
    const int e = blockIdx.x * blockDim.x + threadIdx.x;
    if (e >= E) return;

    const size_t row = (size_t)b * E + e;
    const float4* f = feat + row * 4;

    // Front-batched streaming loads (MLP_p1 = 5), evict-first policy:
    // 230 MB single-use stream should not displace L2 working lines.
    const float4 f0 = __ldcs(f + 0);   // cols 0-3
    const float4 f1 = __ldcs(f + 1);   // cols 4-7
    const float4 f2 = __ldcs(f + 2);   // cols 8-11
    const float4 f3 = __ldcs(f + 3);   // cols 12-15
    const float  bval = __ldcs(base + row);

    // Per-batch physics scalars (warp-uniform; cached)
    const float* p = phys + b * 18;
    const float vel  = p[2];
    const float wall = p[5];
    const float ke   = p[9];
    const float cj   = p[16];
    const float cwj  = p[17];

    // argmax over cols 0..5, first-max-wins (strict >)
    int   et = 0;
    float mx = f0.x;
    if (f0.y > mx) { mx = f0.y; et = 1; }
    if (f0.z > mx) { mx = f0.z; et = 2; }
    if (f0.w > mx) { mx = f0.w; et = 3; }
    if (f1.x > mx) { mx = f1.x; et = 4; }
    if (f1.y > mx) { mx = f1.y; et = 5; }

    const float energy_cost           = f2.z;  // col 10
    const float min_velocity          = f3.x;  // col 12
    const float max_velocity          = f3.y;  // col 13
    const float requires_jump         = f3.z;  // col 14
    const float requires_wall_contact = f3.w;  // col 15

    // jnp.select: first-true-wins priority chain
    const bool cc1 = (et == 1) && (cj < THR);
    const bool cc2 = (et == 3);
    const bool d2  = (wall < THR) || (vel < MIN_VELOCITY_THRESHOLD);
    const bool cc3 = (requires_jump > THR);
    const bool d3  = (cj < THR) || (vel < min_velocity);
    const bool cc4 = (requires_wall_contact > THR);
    const bool d4  = (wall < THR) ||
                     ((cwj < THR) && (vel < MIN_WALL_JUMP_SPEED));
    const bool cc5 = (et == 1);
    const bool d5  = (ke < energy_cost * MIN_JUMP_ENERGY);

    bool dis;
    if      (cc1) dis = true;
    else if (cc2) dis = d2;
    else if (cc3) dis = d3;
    else if (cc4) dis = d4;
    else if (cc5) dis = d5;
    else          dis = false;

    const bool over  = (max_velocity > 0.0f) && (vel > max_velocity);
    const bool under = (!over) && (vel < min_velocity);
    dis = dis || over || under;

    __stcs(out + row, dis ? 0.0f : bval);
}

extern "C" void kernel_launch(void* const* d_in, const int* in_sizes, int n_in,
                              void* d_out, int out_size)
{
    const float4* feat = (const float4*)d_in[0];
    const float*  phys = (const float*) d_in[1];
    const float*  base = (const float*) d_in[2];
    float*        out  = (float*)d_out;

    dim3 block(256);
    dim3 grid((E + 255) / 256, B);   // 391 x 32
    edge_mask_kernel<<<grid, block>>>(feat, phys, base, out);
}